// round 1
// baseline (speedup 1.0000x reference)
#include <cuda_runtime.h>

// DropBlock: out = x * block_mask[h,w] * (3136 / sum(block_mask))
// block_mask = 1 - maxpool_backward_7x7(u < GAMMA)
// GAMMA = 0.1/49 * (56^2 / 50^2) = 0.00256 exactly.

#define H 56
#define W 56
#define HW 3136          // 56*56
#define HW4 784          // HW/4
#define GAMMA 0.00256f

// scratch: mask * scale, packed for float4 loads (12.5 KB, L1/L2 resident)
__device__ float4 g_ms4[HW4];

__global__ void mask_kernel(const float* __restrict__ u) {
    __shared__ float m[HW];
    __shared__ float tot;
    const int tid = threadIdx.x;
    if (tid == 0) tot = 0.0f;
    __syncthreads();

    float local = 0.0f;
    for (int s = tid; s < HW; s += blockDim.x) {
        const int h = s / W;
        const int w = s % W;
        const int h0 = h - 6 < 0 ? 0 : h - 6;
        const int w0 = w - 6 < 0 ? 0 : w - 6;
        float v = 1.0f;   // 1 = keep, 0 = inside a dropped block
        for (int hh = h0; hh <= h; ++hh) {
            #pragma unroll 7
            for (int ww = w0; ww <= w; ++ww) {
                if (__ldg(&u[hh * W + ww]) < GAMMA) v = 0.0f;
            }
        }
        m[s] = v;
        local += v;
    }

    // warp reduce then shared atomic (values are 0/1 -> exact in fp32)
    #pragma unroll
    for (int off = 16; off > 0; off >>= 1)
        local += __shfl_down_sync(0xFFFFFFFFu, local, off);
    if ((tid & 31) == 0) atomicAdd(&tot, local);
    __syncthreads();

    const float scale = (float)HW / tot;
    float* ms = reinterpret_cast<float*>(g_ms4);
    for (int s = tid; s < HW; s += blockDim.x)
        ms[s] = m[s] * scale;
}

__global__ void __launch_bounds__(256) apply_kernel(
    const float4* __restrict__ x, float4* __restrict__ out) {
    const int i = blockIdx.x * blockDim.x + threadIdx.x;  // one float4 per thread
    const int s4 = i % HW4;                               // spatial float4 index
    const float4 mk = g_ms4[s4];
    float4 v = x[i];
    v.x *= mk.x;
    v.y *= mk.y;
    v.z *= mk.z;
    v.w *= mk.w;
    out[i] = v;
}

extern "C" void kernel_launch(void* const* d_in, const int* in_sizes, int n_in,
                              void* d_out, int out_size) {
    const float* x = (const float*)d_in[0];   // (32,256,56,56) f32
    const float* u = (const float*)d_in[1];   // (56,56) f32
    float* out = (float*)d_out;

    mask_kernel<<<1, 1024>>>(u);

    // 32*256*3136 = 25,690,112 floats = 6,422,528 float4 = 25088 blocks * 256
    const int n4 = out_size / 4;
    apply_kernel<<<n4 / 256, 256>>>((const float4*)x, (float4*)out);
}

// round 2
// speedup vs baseline: 1.2608x; 1.2608x over previous
#include <cuda_runtime.h>

// DropBlock: out = x * block_mask[h,w] * (3136 / sum(block_mask))
// block_mask = 1 - backward_7x7_max_dilate(u < GAMMA)
// GAMMA = 0.1/49 * (56^2/50^2) = 0.00256 exactly.
//
// Mask kernel uses bit-parallel separable dilation: each 56-wide row is a
// uint64; row dilation is 3 OR-shift doubling steps, column dilation a
// rolling OR over 7 row words. ~400 int ops replace ~125K scalar loads.

#define H 56
#define W 56
#define HW 3136          // 56*56
#define HW4 784          // HW/4
#define GAMMA 0.00256f

// scratch: mask * scale, packed for float4 loads (12.5 KB, L1/L2 resident)
__device__ float4 g_ms4[HW4];

__global__ void __launch_bounds__(256) mask_kernel(const float* __restrict__ u) {
    __shared__ float su[HW];
    __shared__ unsigned long long dil[H];
    __shared__ unsigned long long rowd[H];
    __shared__ int tot;
    const int tid = threadIdx.x;
    if (tid == 0) tot = 0;

    // coalesced load of u into shared
    for (int s = tid; s < HW; s += 256) su[s] = u[s];
    __syncthreads();

    // row-wise backward dilation (width 7) as bit ops
    if (tid < H) {
        unsigned long long s = 0ULL;
        #pragma unroll
        for (int w = 0; w < W; ++w)
            s |= (unsigned long long)(su[tid * W + w] < GAMMA) << w;
        unsigned long long a = s | (s << 1);      // shifts {0,1}
        unsigned long long b = a | (a << 2);      // shifts {0..3}
        unsigned long long c = b | (b << 3);      // shifts {0..6}
        rowd[tid] = c & ((1ULL << W) - 1ULL);
    }
    __syncthreads();

    // column-wise backward dilation: rolling OR over rows h-6..h, + popcount
    if (tid < H) {
        const int h0 = tid - 6 < 0 ? 0 : tid - 6;
        unsigned long long d = 0ULL;
        for (int h = h0; h <= tid; ++h) d |= rowd[h];
        dil[tid] = d;
        atomicAdd(&tot, __popcll(d));
    }
    __syncthreads();

    const float scale = (float)HW / (float)(HW - tot);
    float* ms = (float*)g_ms4;
    for (int s = tid; s < HW; s += 256) {
        const int h = s / W;
        const int w = s % W;
        ms[s] = ((dil[h] >> w) & 1ULL) ? 0.0f : scale;
    }
}

__global__ void __launch_bounds__(256) apply_kernel(
    const float4* __restrict__ x, float4* __restrict__ out) {
    const int i = blockIdx.x * 512 + threadIdx.x;   // two coalesced float4s/thread
    const int j = i + 256;
    const int s4i = i % HW4;
    const int s4j = j % HW4;
    float4 a = __ldcs(&x[i]);                       // streaming: evict-first
    float4 b = __ldcs(&x[j]);
    const float4 mi = g_ms4[s4i];
    const float4 mj = g_ms4[s4j];
    a.x *= mi.x; a.y *= mi.y; a.z *= mi.z; a.w *= mi.w;
    b.x *= mj.x; b.y *= mj.y; b.z *= mj.z; b.w *= mj.w;
    __stcs(&out[i], a);
    __stcs(&out[j], b);
}

extern "C" void kernel_launch(void* const* d_in, const int* in_sizes, int n_in,
                              void* d_out, int out_size) {
    const float* x = (const float*)d_in[0];   // (32,256,56,56) f32
    const float* u = (const float*)d_in[1];   // (56,56) f32
    float* out = (float*)d_out;

    mask_kernel<<<1, 256>>>(u);

    // 32*256*3136 floats = 6,422,528 float4 = 12544 blocks * 256 threads * 2
    const int n4 = out_size / 4;
    apply_kernel<<<n4 / 512, 256>>>((const float4*)x, (float4*)out);
}